// round 4
// baseline (speedup 1.0000x reference)
#include <cuda_runtime.h>
#include <cooperative_groups.h>
#include <math.h>

namespace cg = cooperative_groups;

// KoLeoLoss — analytic reduction of the flat-stride-diagonal variant.
//
// Math recap (n=1024, d=256): the reference's flat[::n+1]=inf over the
// flattened (n,n,d) tensor excludes the self-pair ONLY at feature k=0,
// and for k=0 excludes exactly j=i. So m[i,k]=0 exactly for k>=1 and
// m[i,0] = min_{j!=i} |y_j - y_i| with y = L2-normalized column 0.
//
//   loss = -( sum_i log(NN_i + eps) + n*(d-1)*log(eps) ) / n
//
// SINGLE kernel node: 8-CTA cluster (one cluster, grid=8), cluster.sync()
// as the grid barrier (HW-backed, no L2 spinning), DSMEM to share y values,
// fixed-order integer-free deterministic reduction to rank 0.

#define KN    1024
#define KD    256
#define KEPS  1e-8f
#define RANKS 8
#define TPB   256   // 8 warps

__global__ void __cluster_dims__(RANKS, 1, 1) __launch_bounds__(TPB, 1)
koleo_cluster_kernel(const float* __restrict__ X, float* __restrict__ out) {
    cg::cluster_group cluster = cg::this_cluster();
    const unsigned rank = cluster.block_rank();

    const int t    = threadIdx.x;
    const int w    = t >> 5;
    const int lane = t & 31;

    __shared__ float  sy[KN];         // all 1024 y values (gathered)
    __shared__ float  s_m[TPB];       // per-thread partial mins
    __shared__ double s_wsum[4];      // per-warp log sums (warps 0..3)
    __shared__ double s_part[RANKS];  // rank 0: per-CTA partial sums

    // ---------------- Phase A: 128 rows per CTA, warp-per-row ----------------
    // Row r: lane reads cols [4*lane,4*lane+4) and [128+4*lane, ...).
    #pragma unroll 4
    for (int it = 0; it < 16; it++) {
        const int row_local = it * 8 + w;
        const int row = (int)rank * 128 + row_local;
        const float4* Xr = (const float4*)(X + row * KD);
        float4 a = Xr[lane];          // lane 0: a.x == X[row*KD + 0]
        float4 c = Xr[lane + 32];
        float ss = a.x*a.x + a.y*a.y + a.z*a.z + a.w*a.w
                 + c.x*c.x + c.y*c.y + c.z*c.z + c.w*c.w;
        #pragma unroll
        for (int o = 16; o > 0; o >>= 1)
            ss += __shfl_xor_sync(0xFFFFFFFFu, ss, o);
        if (lane == 0) {
            float norm = sqrtf(ss);
            sy[(int)rank * 128 + row_local] = a.x / fmaxf(norm, KEPS);
        }
    }

    // Grid barrier #1: all CTAs' own y segments written.
    cluster.sync();

    // ---------------- Gather peers' y segments via DSMEM ----------------
    if (t < 128) {
        #pragma unroll
        for (int p = 0; p < RANKS; p++) {
            if ((unsigned)p != rank) {
                const float* peer = cluster.map_shared_rank((const float*)sy, p);
                sy[p * 128 + t] = peer[p * 128 + t];
            }
        }
    }
    __syncthreads();

    // ---------------- Phase B: 1-D NN for this CTA's 128 i's ----------------
    // Thread t handles i = rank*128 + (t&127), scanning j-half (t>>7).
    const int i_loc  = t & 127;
    const int half   = t >> 7;                 // 0 or 1 (warp-uniform)
    const int i_glob = (int)rank * 128 + i_loc;
    const float xi   = sy[i_glob];
    float m = INFINITY;

    const float4* sv = ((const float4*)sy) + half * 128;
    const int own_half = (int)rank >> 2;       // half containing own segment

    if (half == own_half) {
        // This half contains the self element: exclude j == i_glob.
        const int jbase = half * 512;
        #pragma unroll 8
        for (int q = 0; q < 128; q++) {
            float4 v = sv[q];
            const unsigned rel = (unsigned)(i_glob - (jbase + q * 4));
            if (rel < 4u) ((float*)&v)[rel] = INFINITY;   // rare, once/thread
            m = fminf(m, fabsf(v.x - xi));
            m = fminf(m, fabsf(v.y - xi));
            m = fminf(m, fabsf(v.z - xi));
            m = fminf(m, fabsf(v.w - xi));
        }
    } else {
        // Clean half: no exclusion needed.
        #pragma unroll 8
        for (int q = 0; q < 128; q++) {
            float4 v = sv[q];
            m = fminf(m, fabsf(v.x - xi));
            m = fminf(m, fabsf(v.y - xi));
            m = fminf(m, fabsf(v.z - xi));
            m = fminf(m, fabsf(v.w - xi));
        }
    }
    s_m[t] = m;
    __syncthreads();

    // ---------------- Reduce: logs -> per-CTA double sum ----------------
    if (t < 128) {
        const float mfin = fminf(s_m[t], s_m[t + 128]);
        double l = (double)logf(mfin + KEPS);
        #pragma unroll
        for (int o = 16; o > 0; o >>= 1)
            l += __shfl_xor_sync(0xFFFFFFFFu, l, o);
        if (lane == 0) s_wsum[w] = l;
    }
    __syncthreads();

    if (t == 0) {
        double blk = s_wsum[0] + s_wsum[1] + s_wsum[2] + s_wsum[3];
        double* dst = cluster.map_shared_rank((double*)s_part, 0);
        dst[rank] = blk;
    }

    // Grid barrier #2: all partials landed in rank 0's smem.
    cluster.sync();

    if (rank == 0 && t == 0) {
        double tot = 0.0;
        #pragma unroll
        for (int p = 0; p < RANKS; p++) tot += s_part[p];
        const double cterm = (double)KN * (double)(KD - 1) * log((double)KEPS);
        out[0] = (float)(-(tot + cterm) / (double)KN);
    }
}

extern "C" void kernel_launch(void* const* d_in, const int* in_sizes, int n_in,
                              void* d_out, int out_size) {
    (void)in_sizes; (void)n_in; (void)out_size;
    const float* X = (const float*)d_in[0];
    float* out = (float*)d_out;
    koleo_cluster_kernel<<<RANKS, TPB>>>(X, out);
}

// round 5
// speedup vs baseline: 1.9483x; 1.9483x over previous
#include <cuda_runtime.h>
#include <math.h>

// KoLeoLoss — analytic reduction of the flat-stride-diagonal variant.
//
// Math recap (n=1024, d=256): the reference's flat[::n+1]=inf over the
// flattened (n,n,d) tensor excludes the self-pair ONLY at feature k=0
// (f = i*d*(n+1)+k ≡ k mod 1025), and for k=0 excludes exactly j=i
// (gcd(d,n+1)=1, n ≡ -1). So m[i,k]=0 exactly for k>=1 and
// m[i,0] = min_{j!=i} |y_j - y_i| with y = L2-normalized column 0.
//
//   loss = -( sum_i log(NN_i + eps) + n*(d-1)*log(eps) ) / n
//
// Two kernels chained with PDL (programmatic dependent launch): K2 is
// launched with programmaticStreamSerializationAllowed=1, so its CTAs roll
// out and park in griddepcontrol.wait WHILE K1 runs; K1 signals with
// griddepcontrol.launch_dependents. This hides K2's launch latency — the
// component that kept every previous structure pinned at ~8.6us.

#define KN   1024
#define KD   256
#define KEPS 1e-8f
#define NBLK 128
#define NTHR 256   // 8 warps

__device__ float               g_y[KN];
__device__ int                 g_done = 0;
__device__ unsigned long long  g_sum  = 0ull;

// ---------------- K1: row norms -> g_y (warp-per-row) ----------------
__global__ void __launch_bounds__(NTHR, 1)
koleo_rownorm_kernel(const float* __restrict__ X) {
    const int t    = threadIdx.x;
    const int w    = t >> 5;
    const int lane = t & 31;
    const int row  = blockIdx.x * 8 + w;

    const float4* Xr = (const float4*)(X + row * KD);
    float4 a = Xr[lane];        // lane 0: a.x == X[row*KD + 0]
    float4 c = Xr[lane + 32];
    float ss = a.x*a.x + a.y*a.y + a.z*a.z + a.w*a.w
             + c.x*c.x + c.y*c.y + c.z*c.z + c.w*c.w;
    #pragma unroll
    for (int o = 16; o > 0; o >>= 1)
        ss += __shfl_xor_sync(0xFFFFFFFFu, ss, o);
    if (lane == 0) {
        float norm = sqrtf(ss);
        g_y[row] = a.x / fmaxf(norm, KEPS);
    }
    // Allow the dependent kernel to launch; its griddepcontrol.wait provides
    // the memory-visibility guarantee for g_y.
    asm volatile("griddepcontrol.launch_dependents;");
}

// ---------------- K2: 1-D NN + reduction (warp-per-i) ----------------
__global__ void __launch_bounds__(NTHR, 1)
koleo_nn_kernel(float* __restrict__ out) {
    const int t    = threadIdx.x;
    const int w    = t >> 5;
    const int lane = t & 31;
    const int i    = blockIdx.x * 8 + w;

    __shared__ float sy[KN];
    __shared__ long long psum[8];

    // Park until K1's stores are visible (CTA rollout already happened
    // under K1's execution thanks to PDL).
    asm volatile("griddepcontrol.wait;" ::: "memory");

    // Stage all of g_y (4 KB) into smem: 256 threads x 1 float4.
    ((float4*)sy)[t] = ((const float4*)g_y)[t];
    __syncthreads();

    const float xi = sy[i];
    float m = INFINITY;
    #pragma unroll
    for (int r = 0; r < 32; r++) {
        const int j = r * 32 + lane;          // stride-1 in warp: conflict-free
        const float dd = fabsf(sy[j] - xi);
        if (j != i) m = fminf(m, dd);
    }
    #pragma unroll
    for (int o = 16; o > 0; o >>= 1)
        m = fminf(m, __shfl_xor_sync(0xFFFFFFFFu, m, o));
    if (lane == 0) {
        const float l = logf(m + KEPS);
        psum[w] = (long long)((double)l * 4294967296.0);   // Q32.32
    }
    __syncthreads();

    if (t == 0) {
        long long blk = 0;
        #pragma unroll
        for (int k = 0; k < 8; k++) blk += psum[k];
        atomicAdd(&g_sum, (unsigned long long)blk);
        __threadfence();
        const int old = atomicAdd(&g_done, 1);
        if (old == NBLK - 1) {
            const unsigned long long s = atomicAdd(&g_sum, 0ull);
            const double sum_logs = (double)(long long)s / 4294967296.0;
            const double cterm = (double)(KN * (KD - 1)) * log((double)KEPS);
            out[0] = (float)(-(sum_logs + cterm) / (double)KN);
            g_sum  = 0ull;     // reset for next graph replay
            g_done = 0;
            __threadfence();
        }
    }
}

extern "C" void kernel_launch(void* const* d_in, const int* in_sizes, int n_in,
                              void* d_out, int out_size) {
    (void)in_sizes; (void)n_in; (void)out_size;
    const float* X = (const float*)d_in[0];
    float* out = (float*)d_out;

    koleo_rownorm_kernel<<<NBLK, NTHR>>>(X);

    // K2 with programmatic stream serialization: launch overlaps K1.
    cudaLaunchConfig_t cfg = {};
    cfg.gridDim  = dim3(NBLK, 1, 1);
    cfg.blockDim = dim3(NTHR, 1, 1);
    cfg.dynamicSmemBytes = 0;
    cfg.stream = 0;
    cudaLaunchAttribute attr[1];
    attr[0].id = cudaLaunchAttributeProgrammaticStreamSerialization;
    attr[0].val.programmaticStreamSerializationAllowed = 1;
    cfg.attrs = attr;
    cfg.numAttrs = 1;
    cudaLaunchKernelEx(&cfg, koleo_nn_kernel, out);
}